// round 15
// baseline (speedup 1.0000x reference)
#include <cuda_runtime.h>
#include <math.h>
#include <stdint.h>

#define N_NODES 100000
#define N_EDGES 250000
#define DIN 32
#define DOUT 32
#define DE 13
#define ZC 448          // 14*32 z-columns (13 ea dims + 1 bias slot)
#define ZPITCH 452      // smem z row pitch (floats)
#define XDPF 80         // kFused dup-pair pitch: 4 octets * 20 (bank-disjoint)
#define XDP3 68         // k3 dup-pair pitch (R14-exact)
#define NODES_PER_BLK 32
#define NT 3125         // N_NODES / 32 exactly
#define ECAP 160        // per-tile edge bucket capacity (max deg ~112)
#define KF_THREADS 448  // 14 warps = 14 col-blocks of 32
#define WBLKS 14        // weight-transpose blocks inside kPrep
#define GP 50           // gate smem pitch (u64)

// -------- scratch (device globals: zero-initialized at module load;
//          every kernel_launch invocation restores the zero invariant) -----
__device__ float    g_agg[(size_t)N_NODES * DOUT];  // zeroed by k3 after read
__device__ float    g_cnt[N_NODES];                 // zeroed by k3 after read
__device__ int      g_tcnt[NT];                     // zeroed by kFused after read
__device__ int2     g_ebuf[(size_t)NT * ECAP];      // (dst, (ls<<18)|eid)
__device__ float    g_wbig[32 * ZC];                // pre-transposed Wbig
__device__ uint64_t g_wip[32 * 48];                 // paired w_ih: [k][colpair]
__device__ uint64_t g_whp[32 * 48];                 // paired w_hh: [k][colpair]

// -------- packed f32x2 helpers --------
__device__ __forceinline__ uint64_t pk2(float a, float b) {
    uint64_t r; asm("mov.b64 %0, {%1, %2};" : "=l"(r) : "f"(a), "f"(b)); return r;
}
__device__ __forceinline__ void unpk(uint64_t v, float& a, float& b) {
    asm("mov.b64 {%0, %1}, %2;" : "=f"(a), "=f"(b) : "l"(v));
}
__device__ __forceinline__ void fma2(uint64_t& d, uint64_t a, uint64_t b) {
    asm("fma.rn.f32x2 %0, %1, %2, %0;" : "+l"(d) : "l"(a), "l"(b));
}
__device__ __forceinline__ float fsig(float x) {
    return __fdividef(1.f, 1.f + __expf(-x));
}
__device__ __forceinline__ float ftanh(float x) {
    return __fdividef(2.f, 1.f + __expf(-2.f * x)) - 1.f;
}

// ============================================================
// kPrep: (a) blocks [0,WBLKS): transpose nn_w/nn_b -> g_wbig
//        (b) blocks [WBLKS, WBLKS+2): pair GRU weights
//        (c) remaining blocks: bucket edges by src tile + dst in-degree
// ============================================================
__global__ void kPrep(const int* __restrict__ ei,
                      const float* __restrict__ nn_w,
                      const float* __restrict__ nn_b,
                      const float* __restrict__ w_ih,
                      const float* __restrict__ w_hh) {
    const int b = blockIdx.x;
    const int t = threadIdx.x;
    if (b < WBLKS) {
        for (int idx = b * 256 + t; idx < 32 * ZC; idx += WBLKS * 256) {
            int i = idx / ZC;
            int c = idx - i * ZC;
            int d = c >> 5, o = c & 31;
            g_wbig[idx] = (d < 13) ? nn_w[(i * 32 + o) * 13 + d]
                                   : nn_b[i * 32 + o];
        }
    } else if (b < WBLKS + 2) {
        for (int idx = (b - WBLKS) * 256 + t; idx < 32 * 48; idx += 512) {
            const int k = idx / 48, cp = idx - k * 48;
            g_wip[idx] = pk2(w_ih[(2 * cp) * 32 + k], w_ih[(2 * cp + 1) * 32 + k]);
            g_whp[idx] = pk2(w_hh[(2 * cp) * 32 + k], w_hh[(2 * cp + 1) * 32 + k]);
        }
    } else {
        int e = (b - WBLKS - 2) * 256 + t;
        if (e < N_EDGES) {
            const int src = ei[e];
            const int dst = ei[N_EDGES + e];
            const int tile = src >> 5;
            const int slot = atomicAdd(&g_tcnt[tile], 1);
            if (slot < ECAP)
                g_ebuf[(size_t)tile * ECAP + slot] =
                    make_int2(dst, ((src & 31) << 18) | e);
            atomicAdd(&g_cnt[dst], 1.f);
        }
    }
}

// ============================================================
// kFused: 32-node tile, 14 warps, 2 CTAs/SM.
// ONLY change vs R14: x dup-pair tile uses octet stride 20 floats
// (XDPF=80) so the 4 octet addresses in each LDS.128 hit disjoint
// bank groups ({0-3},{20-23},{8-11},{28-31}).
// ============================================================
__global__ void __launch_bounds__(KF_THREADS, 2)
kFused(const float* __restrict__ x,
       const float* __restrict__ edge_attr) {
    extern __shared__ __align__(16) float sm[];
    float* zs = sm;                          // [32][452]  57856 B
    float* xd = sm + NODES_PER_BLK * ZPITCH; // [32][80]   10240 B (dup pairs)

    const int t = threadIdx.x;    // 448 = 14 warps
    const int lane = t & 31;
    const int w = t >> 5;

    const int ecnt = min(g_tcnt[blockIdx.x], ECAP);

    // stage duplicated-x tile: octet o at col offset o*20, pairs (v,v)
    const int nbase = blockIdx.x * NODES_PER_BLK;
    if (t < 256) {
        const int nl = t >> 3, fq = t & 7;
        const int xoff = (nl >> 3) * 20 + 2 * (nl & 7);
        float4 v = __ldg((const float4*)(x + (size_t)(nbase + nl) * DIN + fq * 4));
        *(uint64_t*)(xd + (size_t)(fq * 4 + 0) * XDPF + xoff) = pk2(v.x, v.x);
        *(uint64_t*)(xd + (size_t)(fq * 4 + 1) * XDPF + xoff) = pk2(v.y, v.y);
        *(uint64_t*)(xd + (size_t)(fq * 4 + 2) * XDPF + xoff) = pk2(v.z, v.z);
        *(uint64_t*)(xd + (size_t)(fq * 4 + 3) * XDPF + xoff) = pk2(v.w, v.w);
    }
    __syncthreads();

    if (t == 0) g_tcnt[blockIdx.x] = 0;   // restore zero invariant

    const int no = lane >> 3;
    const int co = lane & 7;
    const int cbase = w * 32 + co * 4;

    uint64_t acc[16];
#pragma unroll
    for (int q = 0; q < 16; q++) acc[q] = 0ull;

    const float* xrowbase = xd + no * 20;

#pragma unroll 8
    for (int i = 0; i < 32; i++) {
        const ulonglong2 wv =
            __ldg((const ulonglong2*)(g_wbig + (size_t)i * ZC + cbase));
        const ulonglong2* xrow = (const ulonglong2*)(xrowbase + (size_t)i * XDPF);
        const ulonglong2 x01 = xrow[0];
        const ulonglong2 x23 = xrow[1];
        const ulonglong2 x45 = xrow[2];
        const ulonglong2 x67 = xrow[3];

        fma2(acc[0],  x01.x, wv.x); fma2(acc[1],  x01.x, wv.y);
        fma2(acc[2],  x01.y, wv.x); fma2(acc[3],  x01.y, wv.y);
        fma2(acc[4],  x23.x, wv.x); fma2(acc[5],  x23.x, wv.y);
        fma2(acc[6],  x23.y, wv.x); fma2(acc[7],  x23.y, wv.y);
        fma2(acc[8],  x45.x, wv.x); fma2(acc[9],  x45.x, wv.y);
        fma2(acc[10], x45.y, wv.x); fma2(acc[11], x45.y, wv.y);
        fma2(acc[12], x67.x, wv.x); fma2(acc[13], x67.x, wv.y);
        fma2(acc[14], x67.y, wv.x); fma2(acc[15], x67.y, wv.y);
    }

#pragma unroll
    for (int j = 0; j < 8; j++) {
        ulonglong2* zo = (ulonglong2*)(zs + (size_t)(no * 8 + j) * ZPITCH + cbase);
        ulonglong2 s; s.x = acc[j * 2 + 0]; s.y = acc[j * 2 + 1];
        zo[0] = s;
    }
    __syncthreads();

    const int2* ebase = g_ebuf + (size_t)blockIdx.x * ECAP;

    int j = w;
    if (j < ecnt) {
        int2 m = __ldg(&ebase[j]);
        float a = (lane < DE)
                ? __ldg(&edge_attr[(size_t)(m.y & 0x3FFFF) * DE + lane]) : 0.f;

        while (j < ecnt) {
            const int jn = j + 14;
            int2 mn = make_int2(0, 0); float an = 0.f;
            if (jn < ecnt) {
                mn = __ldg(&ebase[jn]);
                an = (lane < DE)
                   ? __ldg(&edge_attr[(size_t)(mn.y & 0x3FFFF) * DE + lane]) : 0.f;
            }

            const int ls = m.y >> 18;
            const float* zr = zs + (size_t)ls * ZPITCH;
            float msg = zr[13 * 32 + lane];
#pragma unroll
            for (int d = 0; d < DE; d++) {
                const float ad = __shfl_sync(0xffffffffu, a, d);
                msg += ad * zr[d * 32 + lane];
            }

            atomicAdd(&g_agg[(size_t)m.x * DOUT + lane], msg);

            j = jn; m = mn; a = an;
        }
    }
}

// ============================================================
// k3 (v4, R14-exact): batched GEMM form, one block per 32-node tile.
// ============================================================
__global__ void __launch_bounds__(256)
k3_gru(const float* __restrict__ x,
       const float* __restrict__ root,
       const float* __restrict__ bias,
       const float* __restrict__ b_ih,
       const float* __restrict__ b_hh,
       float* __restrict__ out,
       int write_h) {
    __shared__ __align__(16) float xd[32 * XDP3];    // dup h pairs [i][2n]
    __shared__ __align__(16) float cd[32 * XDP3];    // dup c pairs [i][2n]
    __shared__ __align__(16) uint64_t gis[32 * GP];  // gi pairs [node][cp]
    __shared__ __align__(16) uint64_t ghs[32 * GP];  // gh pairs [node][cp]

    const int t = threadIdx.x;       // 256
    const int nl = t >> 3;           // node 0..31
    const int fq = t & 7;            // col quad 0..7
    const int n = blockIdx.x * 32 + nl;

    // ---- stage x dup pairs ----
    {
        float4 v = __ldg((const float4*)(x + (size_t)n * DIN + fq * 4));
        *(uint64_t*)(xd + (size_t)(fq * 4 + 0) * XDP3 + 2 * nl) = pk2(v.x, v.x);
        *(uint64_t*)(xd + (size_t)(fq * 4 + 1) * XDP3 + 2 * nl) = pk2(v.y, v.y);
        *(uint64_t*)(xd + (size_t)(fq * 4 + 2) * XDP3 + 2 * nl) = pk2(v.z, v.z);
        *(uint64_t*)(xd + (size_t)(fq * 4 + 3) * XDP3 + 2 * nl) = pk2(v.w, v.w);
    }
    __syncthreads();

    // ---- conv: thread = (node, cols 4fq..4fq+3), K=32 ----
    {
        ulonglong2* ap = (ulonglong2*)(g_agg + (size_t)n * DOUT + fq * 4);
        const ulonglong2 aggv = *ap;
        *ap = make_ulonglong2(0ull, 0ull);        // restore zero invariant
        const float cnt = g_cnt[n];
        if (fq == 0) g_cnt[n] = 0.f;              // restore zero invariant
        const float inv = __fdividef(1.f, fmaxf(cnt, 1.f));
        float a0, a1, a2, a3;
        unpk(aggv.x, a0, a1); unpk(aggv.y, a2, a3);
        const float4 bo = __ldg((const float4*)(bias + fq * 4));
        uint64_t cv01 = pk2(a0 * inv + bo.x, a1 * inv + bo.y);
        uint64_t cv23 = pk2(a2 * inv + bo.z, a3 * inv + bo.w);

#pragma unroll 8
        for (int i = 0; i < 32; i++) {
            const uint64_t xdup = *(const uint64_t*)(xd + (size_t)i * XDP3 + 2 * nl);
            const ulonglong2 rp =
                __ldg((const ulonglong2*)(root + (size_t)i * DOUT + fq * 4));
            fma2(cv01, xdup, rp.x);
            fma2(cv23, xdup, rp.y);
        }
        float c0, c1, c2, c3;
        unpk(cv01, c0, c1); unpk(cv23, c2, c3);
        c0 = (c0 > 0.f) ? c0 : (__expf(c0) - 1.f);
        c1 = (c1 > 0.f) ? c1 : (__expf(c1) - 1.f);
        c2 = (c2 > 0.f) ? c2 : (__expf(c2) - 1.f);
        c3 = (c3 > 0.f) ? c3 : (__expf(c3) - 1.f);
        *(uint64_t*)(cd + (size_t)(fq * 4 + 0) * XDP3 + 2 * nl) = pk2(c0, c0);
        *(uint64_t*)(cd + (size_t)(fq * 4 + 1) * XDP3 + 2 * nl) = pk2(c1, c1);
        *(uint64_t*)(cd + (size_t)(fq * 4 + 2) * XDP3 + 2 * nl) = pk2(c2, c2);
        *(uint64_t*)(cd + (size_t)(fq * 4 + 3) * XDP3 + 2 * nl) = pk2(c3, c3);
    }
    __syncthreads();

    // ---- gate GEMMs: warps 0-2 gi (from cd), warps 3-5 gh (from xd) ----
    const int w = t >> 5;
    const int lane = t & 31;
    if (w < 6) {
        const int gh_side = (w >= 3);
        const int wg = gh_side ? (w - 3) : w;   // 0..2
        const int no = lane >> 3;
        const int co = lane & 7;
        const int cp0 = wg * 16 + 2 * co;       // even colpair base 0..46

        const float* srcb = (gh_side ? xd : cd) + no * 16;
        const uint64_t* wmat = gh_side ? g_whp : g_wip;
        const float* bv = gh_side ? b_hh : b_ih;

        uint64_t acc[16];                       // acc[j*2+p]: node, cp0+p
        {
            const ulonglong2 bp = __ldg((const ulonglong2*)(bv + 2 * cp0));
#pragma unroll
            for (int j = 0; j < 8; j++) { acc[j * 2] = bp.x; acc[j * 2 + 1] = bp.y; }
        }

#pragma unroll 8
        for (int k = 0; k < 32; k++) {
            const ulonglong2 wv =
                __ldg((const ulonglong2*)(wmat + k * 48 + cp0));
            const ulonglong2* sr = (const ulonglong2*)(srcb + (size_t)k * XDP3);
            const ulonglong2 s01 = sr[0], s23 = sr[1], s45 = sr[2], s67 = sr[3];

            fma2(acc[0],  s01.x, wv.x); fma2(acc[1],  s01.x, wv.y);
            fma2(acc[2],  s01.y, wv.x); fma2(acc[3],  s01.y, wv.y);
            fma2(acc[4],  s23.x, wv.x); fma2(acc[5],  s23.x, wv.y);
            fma2(acc[6],  s23.y, wv.x); fma2(acc[7],  s23.y, wv.y);
            fma2(acc[8],  s45.x, wv.x); fma2(acc[9],  s45.x, wv.y);
            fma2(acc[10], s45.y, wv.x); fma2(acc[11], s45.y, wv.y);
            fma2(acc[12], s67.x, wv.x); fma2(acc[13], s67.x, wv.y);
            fma2(acc[14], s67.y, wv.x); fma2(acc[15], s67.y, wv.y);
        }

        uint64_t* dstg = gh_side ? ghs : gis;
#pragma unroll
        for (int j = 0; j < 8; j++) {
            dstg[(no * 8 + j) * GP + cp0]     = acc[j * 2 + 0];
            dstg[(no * 8 + j) * GP + cp0 + 1] = acc[j * 2 + 1];
        }
    }
    __syncthreads();

    // ---- epilogue: thread = (node, output cols 4fq..4fq+3) ----
    {
        const ulonglong2 h0p =
            __ldg((const ulonglong2*)(x + (size_t)n * DIN + fq * 4));
        float h0[4];
        unpk(h0p.x, h0[0], h0[1]); unpk(h0p.y, h0[2], h0[3]);

        float res[4], hnew[4];
#pragma unroll
        for (int q = 0; q < 2; q++) {
            const int c = 2 * fq + q;     // output colpair 0..15
            float ir0, ir1, iz0, iz1, ic0, ic1;
            float hr0, hr1, hz0, hz1, hc0, hc1;
            unpk(gis[nl * GP + c],      ir0, ir1);
            unpk(gis[nl * GP + 16 + c], iz0, iz1);
            unpk(gis[nl * GP + 32 + c], ic0, ic1);
            unpk(ghs[nl * GP + c],      hr0, hr1);
            unpk(ghs[nl * GP + 16 + c], hz0, hz1);
            unpk(ghs[nl * GP + 32 + c], hc0, hc1);

            const float r0 = fsig(ir0 + hr0), r1 = fsig(ir1 + hr1);
            const float z0 = fsig(iz0 + hz0), z1 = fsig(iz1 + hz1);
            const float n0 = ftanh(ic0 + r0 * hc0);
            const float n1 = ftanh(ic1 + r1 * hc1);
            hnew[2 * q + 0] = (1.f - z0) * n0 + z0 * h0[2 * q + 0];
            hnew[2 * q + 1] = (1.f - z1) * n1 + z1 * h0[2 * q + 1];
            res[2 * q + 0] = fmaxf(hnew[2 * q + 0] + h0[2 * q + 0], 0.f);
            res[2 * q + 1] = fmaxf(hnew[2 * q + 1] + h0[2 * q + 1], 0.f);
        }

        *(ulonglong2*)(out + (size_t)n * DOUT + fq * 4) =
            make_ulonglong2(pk2(res[0], res[1]), pk2(res[2], res[3]));
        if (write_h)
            *(ulonglong2*)(out + (size_t)N_NODES * DOUT + (size_t)n * DOUT + fq * 4) =
                make_ulonglong2(pk2(hnew[0], hnew[1]), pk2(hnew[2], hnew[3]));
    }
}

// ============================================================
extern "C" void kernel_launch(void* const* d_in, const int* in_sizes, int n_in,
                              void* d_out, int out_size) {
    const float* x         = (const float*)d_in[0];
    const float* edge_attr = (const float*)d_in[1];
    const float* nn_w      = (const float*)d_in[2];
    const float* nn_b      = (const float*)d_in[3];
    const float* root      = (const float*)d_in[4];
    const float* bias      = (const float*)d_in[5];
    const float* w_ih      = (const float*)d_in[6];
    const float* w_hh      = (const float*)d_in[7];
    const float* b_ih      = (const float*)d_in[8];
    const float* b_hh      = (const float*)d_in[9];
    const int* edge_index  = (const int*)d_in[10];
    float* out = (float*)d_out;

    const int smemF = (NODES_PER_BLK * ZPITCH + 32 * XDPF) * (int)sizeof(float); // 68096
    cudaFuncSetAttribute(kFused, cudaFuncAttributeMaxDynamicSharedMemorySize, smemF);

    const int gridE = (N_EDGES + 255) / 256;      // 977

    kPrep<<<WBLKS + 2 + gridE, 256>>>(edge_index, nn_w, nn_b, w_ih, w_hh); // 1
    kFused<<<NT, KF_THREADS, smemF>>>(x, edge_attr);                       // 2
    const int write_h = (out_size >= 2 * N_NODES * DOUT) ? 1 : 0;
    k3_gru<<<NT, 256>>>(x, root, bias, b_ih, b_hh, out, write_h);          // 3
}

// round 16
// speedup vs baseline: 1.0618x; 1.0618x over previous
#include <cuda_runtime.h>
#include <math.h>
#include <stdint.h>

#define N_NODES 100000
#define N_EDGES 250000
#define DIN 32
#define DOUT 32
#define DE 13
#define ZC 448          // 14*32 z-columns (13 ea dims + 1 bias slot)
#define ZPITCH 452      // smem z row pitch (floats)
#define XDP 68          // duplicated-pair row pitch (floats) — R14-exact
#define NODES_PER_BLK 32
#define NT 3125         // N_NODES / 32 exactly
#define ECAP 160        // per-tile edge bucket capacity (max deg ~112)
#define KF_THREADS 448  // 14 warps = 14 col-blocks of 32
#define WBLKS 14        // weight-transpose blocks inside kPrep
#define GP 50           // gate smem pitch (u64)

// -------- scratch (device globals: zero-initialized at module load;
//          every kernel_launch invocation restores the zero invariant) -----
__device__ float    g_agg[(size_t)N_NODES * DOUT];  // zeroed by k3 after read
__device__ float    g_cnt[N_NODES];                 // zeroed by k3 after read
__device__ int      g_tcnt[NT];                     // zeroed by kFused after read
__device__ int2     g_ebuf[(size_t)NT * ECAP];      // (dst, (ls<<18)|eid)
__device__ float    g_wbig[32 * ZC];                // pre-transposed Wbig
__device__ uint64_t g_wip[32 * 48];                 // paired w_ih: [k][colpair]
__device__ uint64_t g_whp[32 * 48];                 // paired w_hh: [k][colpair]

// -------- packed f32x2 helpers --------
__device__ __forceinline__ uint64_t pk2(float a, float b) {
    uint64_t r; asm("mov.b64 %0, {%1, %2};" : "=l"(r) : "f"(a), "f"(b)); return r;
}
__device__ __forceinline__ void unpk(uint64_t v, float& a, float& b) {
    asm("mov.b64 {%0, %1}, %2;" : "=f"(a), "=f"(b) : "l"(v));
}
__device__ __forceinline__ void fma2(uint64_t& d, uint64_t a, uint64_t b) {
    asm("fma.rn.f32x2 %0, %1, %2, %0;" : "+l"(d) : "l"(a), "l"(b));
}
__device__ __forceinline__ float fsig(float x) {
    return __fdividef(1.f, 1.f + __expf(-x));
}
__device__ __forceinline__ float ftanh(float x) {
    return __fdividef(2.f, 1.f + __expf(-2.f * x)) - 1.f;
}

// ============================================================
// kPrep: (a) blocks [0,WBLKS): transpose nn_w/nn_b -> g_wbig
//        (b) blocks [WBLKS, WBLKS+2): pair GRU weights
//        (c) remaining blocks: bucket edges by src tile + dst in-degree
// ============================================================
__global__ void kPrep(const int* __restrict__ ei,
                      const float* __restrict__ nn_w,
                      const float* __restrict__ nn_b,
                      const float* __restrict__ w_ih,
                      const float* __restrict__ w_hh) {
    const int b = blockIdx.x;
    const int t = threadIdx.x;
    if (b < WBLKS) {
        for (int idx = b * 256 + t; idx < 32 * ZC; idx += WBLKS * 256) {
            int i = idx / ZC;
            int c = idx - i * ZC;
            int d = c >> 5, o = c & 31;
            g_wbig[idx] = (d < 13) ? nn_w[(i * 32 + o) * 13 + d]
                                   : nn_b[i * 32 + o];
        }
    } else if (b < WBLKS + 2) {
        for (int idx = (b - WBLKS) * 256 + t; idx < 32 * 48; idx += 512) {
            const int k = idx / 48, cp = idx - k * 48;
            g_wip[idx] = pk2(w_ih[(2 * cp) * 32 + k], w_ih[(2 * cp + 1) * 32 + k]);
            g_whp[idx] = pk2(w_hh[(2 * cp) * 32 + k], w_hh[(2 * cp + 1) * 32 + k]);
        }
    } else {
        int e = (b - WBLKS - 2) * 256 + t;
        if (e < N_EDGES) {
            const int src = ei[e];
            const int dst = ei[N_EDGES + e];
            const int tile = src >> 5;
            const int slot = atomicAdd(&g_tcnt[tile], 1);
            if (slot < ECAP)
                g_ebuf[(size_t)tile * ECAP + slot] =
                    make_int2(dst, ((src & 31) << 18) | e);
            atomicAdd(&g_cnt[dst], 1.f);
        }
    }
}

// ============================================================
// kFused: 32-node tile, 14 warps, 2 CTAs/SM.  Phase 1 = R14-exact.
// Phase 2 (NEW): 2 edges per warp — half-warp per edge, lane = channel
// pair, f32x2 accumulate. SHFL/LDS run unconditionally (convergent);
// only the atomic scatter is predicated on edge validity.
// ============================================================
__global__ void __launch_bounds__(KF_THREADS, 2)
kFused(const float* __restrict__ x,
       const float* __restrict__ edge_attr) {
    extern __shared__ __align__(16) float sm[];
    float* zs = sm;                          // [32][452]  57856 B
    float* xd = sm + NODES_PER_BLK * ZPITCH; // [32][68]    8704 B (dup pairs)

    const int t = threadIdx.x;    // 448 = 14 warps
    const int lane = t & 31;
    const int w = t >> 5;

    const int ecnt = min(g_tcnt[blockIdx.x], ECAP);

    const int nbase = blockIdx.x * NODES_PER_BLK;
    if (t < 256) {
        const int nl = t >> 3, fq = t & 7;
        float4 v = __ldg((const float4*)(x + (size_t)(nbase + nl) * DIN + fq * 4));
        *(uint64_t*)(xd + (size_t)(fq * 4 + 0) * XDP + 2 * nl) = pk2(v.x, v.x);
        *(uint64_t*)(xd + (size_t)(fq * 4 + 1) * XDP + 2 * nl) = pk2(v.y, v.y);
        *(uint64_t*)(xd + (size_t)(fq * 4 + 2) * XDP + 2 * nl) = pk2(v.z, v.z);
        *(uint64_t*)(xd + (size_t)(fq * 4 + 3) * XDP + 2 * nl) = pk2(v.w, v.w);
    }
    __syncthreads();

    if (t == 0) g_tcnt[blockIdx.x] = 0;   // restore zero invariant

    const int no = lane >> 3;
    const int co = lane & 7;
    const int cbase = w * 32 + co * 4;

    uint64_t acc[16];
#pragma unroll
    for (int q = 0; q < 16; q++) acc[q] = 0ull;

    const float* xrowbase = xd + no * 16;

#pragma unroll 8
    for (int i = 0; i < 32; i++) {
        const ulonglong2 wv =
            __ldg((const ulonglong2*)(g_wbig + (size_t)i * ZC + cbase));
        const ulonglong2* xrow = (const ulonglong2*)(xrowbase + (size_t)i * XDP);
        const ulonglong2 x01 = xrow[0];
        const ulonglong2 x23 = xrow[1];
        const ulonglong2 x45 = xrow[2];
        const ulonglong2 x67 = xrow[3];

        fma2(acc[0],  x01.x, wv.x); fma2(acc[1],  x01.x, wv.y);
        fma2(acc[2],  x01.y, wv.x); fma2(acc[3],  x01.y, wv.y);
        fma2(acc[4],  x23.x, wv.x); fma2(acc[5],  x23.x, wv.y);
        fma2(acc[6],  x23.y, wv.x); fma2(acc[7],  x23.y, wv.y);
        fma2(acc[8],  x45.x, wv.x); fma2(acc[9],  x45.x, wv.y);
        fma2(acc[10], x45.y, wv.x); fma2(acc[11], x45.y, wv.y);
        fma2(acc[12], x67.x, wv.x); fma2(acc[13], x67.x, wv.y);
        fma2(acc[14], x67.y, wv.x); fma2(acc[15], x67.y, wv.y);
    }

#pragma unroll
    for (int j = 0; j < 8; j++) {
        ulonglong2* zo = (ulonglong2*)(zs + (size_t)(no * 8 + j) * ZPITCH + cbase);
        ulonglong2 s; s.x = acc[j * 2 + 0]; s.y = acc[j * 2 + 1];
        zo[0] = s;
    }
    __syncthreads();

    // ---- phase 2: 2 edges per warp (half-warp per edge), f32x2 ----
    const int2* ebase = g_ebuf + (size_t)blockIdx.x * ECAP;
    const int half = lane >> 4;      // which edge of the pair
    const int c = lane & 15;         // channel pair index
    const int cc = 2 * c;

    int jb = w * 2;                  // pair base for this warp
    if (jb < ecnt) {
        int j = jb + half;
        bool v = (j < ecnt);
        int2 m = make_int2(0, 0); float a = 0.f;
        if (v) {
            m = __ldg(&ebase[j]);
            if (c < DE) a = __ldg(&edge_attr[(size_t)(m.y & 0x3FFFF) * DE + c]);
        }

        while (jb < ecnt) {
            // prefetch next pair
            const int jn = j + 28;
            const bool vn = (jn < ecnt);
            int2 mn = make_int2(0, 0); float an = 0.f;
            if (vn) {
                mn = __ldg(&ebase[jn]);
                if (c < DE)
                    an = __ldg(&edge_attr[(size_t)(mn.y & 0x3FFFF) * DE + c]);
            }

            const int ls = m.y >> 18;     // 0 for invalid halves (safe row)
            const float* zr = zs + (size_t)ls * ZPITCH;
            uint64_t msg2 = *(const uint64_t*)(zr + 13 * 32 + cc);  // bias
#pragma unroll
            for (int d = 0; d < DE; d++) {
                const float ad = __shfl_sync(0xffffffffu, a, d, 16);
                fma2(msg2, pk2(ad, ad), *(const uint64_t*)(zr + d * 32 + cc));
            }

            if (v) {
                float m0, m1; unpk(msg2, m0, m1);
                float* dp = &g_agg[(size_t)m.x * DOUT + cc];
                atomicAdd(dp, m0);
                atomicAdd(dp + 1, m1);
            }

            jb += 28; j = jn; v = vn; m = mn; a = an;
        }
    }
}

// ============================================================
// k3 (v4, R14-exact): batched GEMM form, one block per 32-node tile.
// ============================================================
__global__ void __launch_bounds__(256)
k3_gru(const float* __restrict__ x,
       const float* __restrict__ root,
       const float* __restrict__ bias,
       const float* __restrict__ b_ih,
       const float* __restrict__ b_hh,
       float* __restrict__ out,
       int write_h) {
    __shared__ __align__(16) float xd[32 * XDP];     // dup h pairs [i][2n]
    __shared__ __align__(16) float cd[32 * XDP];     // dup c pairs [i][2n]
    __shared__ __align__(16) uint64_t gis[32 * GP];  // gi pairs [node][cp]
    __shared__ __align__(16) uint64_t ghs[32 * GP];  // gh pairs [node][cp]

    const int t = threadIdx.x;       // 256
    const int nl = t >> 3;           // node 0..31
    const int fq = t & 7;            // col quad 0..7
    const int n = blockIdx.x * 32 + nl;

    // ---- stage x dup pairs ----
    {
        float4 v = __ldg((const float4*)(x + (size_t)n * DIN + fq * 4));
        *(uint64_t*)(xd + (size_t)(fq * 4 + 0) * XDP + 2 * nl) = pk2(v.x, v.x);
        *(uint64_t*)(xd + (size_t)(fq * 4 + 1) * XDP + 2 * nl) = pk2(v.y, v.y);
        *(uint64_t*)(xd + (size_t)(fq * 4 + 2) * XDP + 2 * nl) = pk2(v.z, v.z);
        *(uint64_t*)(xd + (size_t)(fq * 4 + 3) * XDP + 2 * nl) = pk2(v.w, v.w);
    }
    __syncthreads();

    // ---- conv: thread = (node, cols 4fq..4fq+3), K=32 ----
    {
        ulonglong2* ap = (ulonglong2*)(g_agg + (size_t)n * DOUT + fq * 4);
        const ulonglong2 aggv = *ap;
        *ap = make_ulonglong2(0ull, 0ull);        // restore zero invariant
        const float cnt = g_cnt[n];
        if (fq == 0) g_cnt[n] = 0.f;              // restore zero invariant
        const float inv = __fdividef(1.f, fmaxf(cnt, 1.f));
        float a0, a1, a2, a3;
        unpk(aggv.x, a0, a1); unpk(aggv.y, a2, a3);
        const float4 bo = __ldg((const float4*)(bias + fq * 4));
        uint64_t cv01 = pk2(a0 * inv + bo.x, a1 * inv + bo.y);
        uint64_t cv23 = pk2(a2 * inv + bo.z, a3 * inv + bo.w);

#pragma unroll 8
        for (int i = 0; i < 32; i++) {
            const uint64_t xdup = *(const uint64_t*)(xd + (size_t)i * XDP + 2 * nl);
            const ulonglong2 rp =
                __ldg((const ulonglong2*)(root + (size_t)i * DOUT + fq * 4));
            fma2(cv01, xdup, rp.x);
            fma2(cv23, xdup, rp.y);
        }
        float c0, c1, c2, c3;
        unpk(cv01, c0, c1); unpk(cv23, c2, c3);
        c0 = (c0 > 0.f) ? c0 : (__expf(c0) - 1.f);
        c1 = (c1 > 0.f) ? c1 : (__expf(c1) - 1.f);
        c2 = (c2 > 0.f) ? c2 : (__expf(c2) - 1.f);
        c3 = (c3 > 0.f) ? c3 : (__expf(c3) - 1.f);
        *(uint64_t*)(cd + (size_t)(fq * 4 + 0) * XDP + 2 * nl) = pk2(c0, c0);
        *(uint64_t*)(cd + (size_t)(fq * 4 + 1) * XDP + 2 * nl) = pk2(c1, c1);
        *(uint64_t*)(cd + (size_t)(fq * 4 + 2) * XDP + 2 * nl) = pk2(c2, c2);
        *(uint64_t*)(cd + (size_t)(fq * 4 + 3) * XDP + 2 * nl) = pk2(c3, c3);
    }
    __syncthreads();

    // ---- gate GEMMs: warps 0-2 gi (from cd), warps 3-5 gh (from xd) ----
    const int w = t >> 5;
    const int lane = t & 31;
    if (w < 6) {
        const int gh_side = (w >= 3);
        const int wg = gh_side ? (w - 3) : w;   // 0..2
        const int no = lane >> 3;
        const int co = lane & 7;
        const int cp0 = wg * 16 + 2 * co;       // even colpair base 0..46

        const float* srcb = (gh_side ? xd : cd) + no * 16;
        const uint64_t* wmat = gh_side ? g_whp : g_wip;
        const float* bv = gh_side ? b_hh : b_ih;

        uint64_t acc[16];                       // acc[j*2+p]: node, cp0+p
        {
            const ulonglong2 bp = __ldg((const ulonglong2*)(bv + 2 * cp0));
#pragma unroll
            for (int j = 0; j < 8; j++) { acc[j * 2] = bp.x; acc[j * 2 + 1] = bp.y; }
        }

#pragma unroll 8
        for (int k = 0; k < 32; k++) {
            const ulonglong2 wv =
                __ldg((const ulonglong2*)(wmat + k * 48 + cp0));
            const ulonglong2* sr = (const ulonglong2*)(srcb + (size_t)k * XDP);
            const ulonglong2 s01 = sr[0], s23 = sr[1], s45 = sr[2], s67 = sr[3];

            fma2(acc[0],  s01.x, wv.x); fma2(acc[1],  s01.x, wv.y);
            fma2(acc[2],  s01.y, wv.x); fma2(acc[3],  s01.y, wv.y);
            fma2(acc[4],  s23.x, wv.x); fma2(acc[5],  s23.x, wv.y);
            fma2(acc[6],  s23.y, wv.x); fma2(acc[7],  s23.y, wv.y);
            fma2(acc[8],  s45.x, wv.x); fma2(acc[9],  s45.x, wv.y);
            fma2(acc[10], s45.y, wv.x); fma2(acc[11], s45.y, wv.y);
            fma2(acc[12], s67.x, wv.x); fma2(acc[13], s67.x, wv.y);
            fma2(acc[14], s67.y, wv.x); fma2(acc[15], s67.y, wv.y);
        }

        uint64_t* dstg = gh_side ? ghs : gis;
#pragma unroll
        for (int j = 0; j < 8; j++) {
            dstg[(no * 8 + j) * GP + cp0]     = acc[j * 2 + 0];
            dstg[(no * 8 + j) * GP + cp0 + 1] = acc[j * 2 + 1];
        }
    }
    __syncthreads();

    // ---- epilogue: thread = (node, output cols 4fq..4fq+3) ----
    {
        const ulonglong2 h0p =
            __ldg((const ulonglong2*)(x + (size_t)n * DIN + fq * 4));
        float h0[4];
        unpk(h0p.x, h0[0], h0[1]); unpk(h0p.y, h0[2], h0[3]);

        float res[4], hnew[4];
#pragma unroll
        for (int q = 0; q < 2; q++) {
            const int c = 2 * fq + q;     // output colpair 0..15
            float ir0, ir1, iz0, iz1, ic0, ic1;
            float hr0, hr1, hz0, hz1, hc0, hc1;
            unpk(gis[nl * GP + c],      ir0, ir1);
            unpk(gis[nl * GP + 16 + c], iz0, iz1);
            unpk(gis[nl * GP + 32 + c], ic0, ic1);
            unpk(ghs[nl * GP + c],      hr0, hr1);
            unpk(ghs[nl * GP + 16 + c], hz0, hz1);
            unpk(ghs[nl * GP + 32 + c], hc0, hc1);

            const float r0 = fsig(ir0 + hr0), r1 = fsig(ir1 + hr1);
            const float z0 = fsig(iz0 + hz0), z1 = fsig(iz1 + hz1);
            const float n0 = ftanh(ic0 + r0 * hc0);
            const float n1 = ftanh(ic1 + r1 * hc1);
            hnew[2 * q + 0] = (1.f - z0) * n0 + z0 * h0[2 * q + 0];
            hnew[2 * q + 1] = (1.f - z1) * n1 + z1 * h0[2 * q + 1];
            res[2 * q + 0] = fmaxf(hnew[2 * q + 0] + h0[2 * q + 0], 0.f);
            res[2 * q + 1] = fmaxf(hnew[2 * q + 1] + h0[2 * q + 1], 0.f);
        }

        *(ulonglong2*)(out + (size_t)n * DOUT + fq * 4) =
            make_ulonglong2(pk2(res[0], res[1]), pk2(res[2], res[3]));
        if (write_h)
            *(ulonglong2*)(out + (size_t)N_NODES * DOUT + (size_t)n * DOUT + fq * 4) =
                make_ulonglong2(pk2(hnew[0], hnew[1]), pk2(hnew[2], hnew[3]));
    }
}

// ============================================================
extern "C" void kernel_launch(void* const* d_in, const int* in_sizes, int n_in,
                              void* d_out, int out_size) {
    const float* x         = (const float*)d_in[0];
    const float* edge_attr = (const float*)d_in[1];
    const float* nn_w      = (const float*)d_in[2];
    const float* nn_b      = (const float*)d_in[3];
    const float* root      = (const float*)d_in[4];
    const float* bias      = (const float*)d_in[5];
    const float* w_ih      = (const float*)d_in[6];
    const float* w_hh      = (const float*)d_in[7];
    const float* b_ih      = (const float*)d_in[8];
    const float* b_hh      = (const float*)d_in[9];
    const int* edge_index  = (const int*)d_in[10];
    float* out = (float*)d_out;

    const int smemF = (NODES_PER_BLK * ZPITCH + 32 * XDP) * (int)sizeof(float); // 66560
    cudaFuncSetAttribute(kFused, cudaFuncAttributeMaxDynamicSharedMemorySize, smemF);

    const int gridE = (N_EDGES + 255) / 256;      // 977

    kPrep<<<WBLKS + 2 + gridE, 256>>>(edge_index, nn_w, nn_b, w_ih, w_hh); // 1
    kFused<<<NT, KF_THREADS, smemF>>>(x, edge_attr);                       // 2
    const int write_h = (out_size >= 2 * N_NODES * DOUT) ? 1 : 0;
    k3_gru<<<NT, 256>>>(x, root, bias, b_ih, b_hh, out, write_h);          // 3
}